// round 4
// baseline (speedup 1.0000x reference)
#include <cuda_runtime.h>
#include <math.h>

#define MAXN 50000
#define MAXE 800000
#define MAXR 2000
#define FF   128
#define FD   384
#define PP   64
#define EPSV 1e-12f

// ------------------------ scratch (device globals, no allocs) ------------------
__device__ int   g_deg[MAXN];
__device__ int   g_rowptr[MAXN + 1];
__device__ int   g_cursor[MAXN];
__device__ int2  g_edge[MAXE];                  // (src, rel) in CSR-by-dst order
__device__ float g_relnorm[MAXR * FF];
__device__ float g_ttab[4 * MAXR];
__device__ float g_smax[4 * MAXN];
__device__ float g_ssum[4 * MAXN];
__device__ float g_out[2][(size_t)MAXN * FD];
__device__ float g_pf[2][(size_t)MAXN * FD];
__device__ float g_pn[2][PP * FD];              // l2-normalized proxy rows
__device__ float g_att[2][(size_t)MAXN * PP];   // softmaxed attention

__device__ __forceinline__ float wsum(float v) {
#pragma unroll
    for (int o = 16; o; o >>= 1) v += __shfl_xor_sync(0xffffffffu, v, o);
    return v;
}
__device__ __forceinline__ float wmax(float v) {
#pragma unroll
    for (int o = 16; o; o >>= 1) v = fmaxf(v, __shfl_xor_sync(0xffffffffu, v, o));
    return v;
}

// ------------------------ packed f32x2 helpers ---------------------------------
__device__ __forceinline__ unsigned long long pack2(float x) {
    unsigned long long r;
    unsigned u = __float_as_uint(x);
    asm("mov.b64 %0, {%1, %1};" : "=l"(r) : "r"(u));
    return r;
}
__device__ __forceinline__ void fma2(unsigned long long& d, unsigned long long a,
                                     unsigned long long b) {
    asm("fma.rn.f32x2 %0, %1, %2, %0;" : "+l"(d) : "l"(a), "l"(b));
}
__device__ __forceinline__ float lo32(unsigned long long v) {
    return __uint_as_float((unsigned)v);
}
__device__ __forceinline__ float hi32(unsigned long long v) {
    return __uint_as_float((unsigned)(v >> 32));
}

// ------------------------ CSR build ------------------------
__global__ void zero_deg_kernel(int N_) {
    int i = blockIdx.x * blockDim.x + threadIdx.x;
    if (i < N_) g_deg[i] = 0;
}

__global__ void count_kernel(const int* __restrict__ edst, int E_) {
    int e = blockIdx.x * blockDim.x + threadIdx.x;
    if (e < E_) atomicAdd(&g_deg[edst[e]], 1);
}

__global__ void scan_kernel(int N_) {
    __shared__ int sh[1024];
    __shared__ int carry;
    if (threadIdx.x == 0) carry = 0;
    __syncthreads();
    for (int base = 0; base < N_; base += 1024) {
        int i = base + threadIdx.x;
        int v = (i < N_) ? g_deg[i] : 0;
        sh[threadIdx.x] = v;
        __syncthreads();
#pragma unroll
        for (int off = 1; off < 1024; off <<= 1) {
            int t = (threadIdx.x >= off) ? sh[threadIdx.x - off] : 0;
            __syncthreads();
            sh[threadIdx.x] += t;
            __syncthreads();
        }
        int inc = sh[threadIdx.x];
        int exc = inc - v + carry;
        if (i < N_) { g_rowptr[i] = exc; g_cursor[i] = exc; }
        __syncthreads();
        if (threadIdx.x == 1023) carry += sh[1023];
        __syncthreads();
    }
    if (threadIdx.x == 0) g_rowptr[N_] = carry;
}

__global__ void scatter_kernel(const int* __restrict__ edst,
                               const int* __restrict__ esrc,
                               const int* __restrict__ erel, int E_) {
    int e = blockIdx.x * blockDim.x + threadIdx.x;
    if (e < E_) {
        int p = atomicAdd(&g_cursor[edst[e]], 1);
        g_edge[p] = make_int2(esrc[e], erel[e]);
    }
}

// ------------------------ relation normalization + attn tables ------------------
__global__ void relnorm_kernel(const float* __restrict__ rel,
                               const float* __restrict__ attn_e,
                               const float* __restrict__ attn_r, int R_) {
    int w = (blockIdx.x * blockDim.x + threadIdx.x) >> 5;
    int lane = threadIdx.x & 31;
    if (w >= R_) return;
    float4 v = *(const float4*)(rel + (size_t)w * FF + lane * 4);
    float ss = v.x * v.x + v.y * v.y + v.z * v.z + v.w * v.w;
    ss = wsum(ss);
    float inv = 1.f / fmaxf(sqrtf(ss), EPSV);
    float4 rn = make_float4(v.x * inv, v.y * inv, v.z * inv, v.w * inv);
    *(float4*)(g_relnorm + (size_t)w * FF + lane * 4) = rn;

    float4 a0 = *(const float4*)(attn_e + lane * 4);
    float4 a1 = *(const float4*)(attn_e + FF + lane * 4);
    float4 a2 = *(const float4*)(attn_r + lane * 4);
    float4 a3 = *(const float4*)(attn_r + FF + lane * 4);
    float d0 = wsum(rn.x * a0.x + rn.y * a0.y + rn.z * a0.z + rn.w * a0.w);
    float d1 = wsum(rn.x * a1.x + rn.y * a1.y + rn.z * a1.z + rn.w * a1.w);
    float d2 = wsum(rn.x * a2.x + rn.y * a2.y + rn.z * a2.z + rn.w * a2.w);
    float d3 = wsum(rn.x * a3.x + rn.y * a3.y + rn.z * a3.z + rn.w * a3.w);
    if (lane == 0) {
        g_ttab[0 * R_ + w] = d0;
        g_ttab[1 * R_ + w] = d1;
        g_ttab[2 * R_ + w] = d2;
        g_ttab[3 * R_ + w] = d3;
    }
}

// ------------------------ edge-softmax stats (all 4 tables at once) -------------
__global__ void __launch_bounds__(256) stats_kernel(int N_, int R_) {
    __shared__ float tab[4 * MAXR];
    int tid = threadIdx.x;
    for (int i = tid; i < 4 * R_; i += blockDim.x) tab[i] = g_ttab[i];
    __syncthreads();
    int warp = tid >> 5, lane = tid & 31;
    for (int n = blockIdx.x * 8 + warp; n < N_; n += gridDim.x * 8) {
        int s = g_rowptr[n], e = g_rowptr[n + 1];
        float m0 = -1e30f, m1 = -1e30f, m2 = -1e30f, m3 = -1e30f;
        for (int i = s + lane; i < e; i += 32) {
            int r = g_edge[i].y;
            m0 = fmaxf(m0, tab[r]);
            m1 = fmaxf(m1, tab[R_ + r]);
            m2 = fmaxf(m2, tab[2 * R_ + r]);
            m3 = fmaxf(m3, tab[3 * R_ + r]);
        }
        m0 = wmax(m0); m1 = wmax(m1); m2 = wmax(m2); m3 = wmax(m3);
        float s0 = 0, s1 = 0, s2 = 0, s3 = 0;
        for (int i = s + lane; i < e; i += 32) {
            int r = g_edge[i].y;
            s0 += __expf(tab[r] - m0);
            s1 += __expf(tab[R_ + r] - m1);
            s2 += __expf(tab[2 * R_ + r] - m2);
            s3 += __expf(tab[3 * R_ + r] - m3);
        }
        s0 = wsum(s0); s1 = wsum(s1); s2 = wsum(s2); s3 = wsum(s3);
        if (lane == 0) {
            g_smax[0 * N_ + n] = m0; g_ssum[0 * N_ + n] = s0;
            g_smax[1 * N_ + n] = m1; g_ssum[1 * N_ + n] = s1;
            g_smax[2 * N_ + n] = m2; g_ssum[2 * N_ + n] = s2;
            g_smax[3 * N_ + n] = m3; g_ssum[3 * N_ + n] = s3;
        }
    }
}

// ------------------------ initial mean features: 4 edges / warp -----------------
__global__ void __launch_bounds__(256) init_kernel(const float* __restrict__ ent,
                                                   const float* __restrict__ rel, int N_) {
    int w = (blockIdx.x * blockDim.x + threadIdx.x) >> 5;
    if (w >= N_) return;
    int lane = threadIdx.x & 31;
    int sub = lane >> 3, l8 = lane & 7;
    int s = g_rowptr[w], e = g_rowptr[w + 1];
    float ae[16], ar[16];
#pragma unroll
    for (int j = 0; j < 16; j++) { ae[j] = 0.f; ar[j] = 0.f; }
    for (int i = s; i < e; i += 4) {
        int idx = min(i + sub, e - 1);
        float act = (i + sub < e) ? 1.f : 0.f;
        int2 ed = g_edge[idx];
        const float* fe = ent + (size_t)ed.x * FF + l8 * 16;
        const float* fr = rel + (size_t)ed.y * FF + l8 * 16;
#pragma unroll
        for (int q = 0; q < 4; q++) {
            float4 ve = *(const float4*)(fe + q * 4);
            float4 vr = *(const float4*)(fr + q * 4);
            ae[q * 4 + 0] += act * ve.x; ae[q * 4 + 1] += act * ve.y;
            ae[q * 4 + 2] += act * ve.z; ae[q * 4 + 3] += act * ve.w;
            ar[q * 4 + 0] += act * vr.x; ar[q * 4 + 1] += act * vr.y;
            ar[q * 4 + 2] += act * vr.z; ar[q * 4 + 3] += act * vr.w;
        }
    }
#pragma unroll
    for (int j = 0; j < 16; j++) {
        ae[j] += __shfl_xor_sync(0xffffffffu, ae[j], 8);
        ae[j] += __shfl_xor_sync(0xffffffffu, ae[j], 16);
        ar[j] += __shfl_xor_sync(0xffffffffu, ar[j], 8);
        ar[j] += __shfl_xor_sync(0xffffffffu, ar[j], 16);
    }
    if (sub == 0) {
        float inv = 1.f / fmaxf((float)(e - s), 1.f);
        float* oe = &g_out[0][(size_t)w * FD + l8 * 16];
        float* orr = &g_out[1][(size_t)w * FD + l8 * 16];
#pragma unroll
        for (int j = 0; j < 16; j++) {
            oe[j] = tanhf(ae[j] * inv);
            orr[j] = tanhf(ar[j] * inv);
        }
    }
}

// ------------------------ GNN layer: 4 edges / warp, 8 lanes / edge -------------
__global__ void __launch_bounds__(256) layer_kernel(int layer, int N_, int R_) {
    int gw = (blockIdx.x * blockDim.x + threadIdx.x) >> 5;
    if (gw >= 2 * N_) return;
    int dual = gw >= N_;
    int w = gw - dual * N_;
    int lane = threadIdx.x & 31;
    int sub = lane >> 3, l8 = lane & 7;
    int s = g_rowptr[w], e = g_rowptr[w + 1];
    int t = dual * 2 + layer;
    const float* feats = g_out[dual];
    const float* tt = g_ttab + (size_t)t * R_;
    float smax = g_smax[(size_t)t * N_ + w];
    float invs = (e > s) ? 1.f / g_ssum[(size_t)t * N_ + w] : 0.f;
    int coff = layer * FF + l8 * 16;

    float acc[16];
#pragma unroll
    for (int j = 0; j < 16; j++) acc[j] = 0.f;

    for (int i = s; i < e; i += 4) {
        int idx = min(i + sub, e - 1);
        float act = (i + sub < e) ? 1.f : 0.f;
        int2 ed = g_edge[idx];
        const float* fp = feats + (size_t)ed.x * FD + coff;
        const float* rp = g_relnorm + (size_t)ed.y * FF + l8 * 16;
        float f[16], rn[16];
#pragma unroll
        for (int q = 0; q < 4; q++) {
            float4 vf = *(const float4*)(fp + q * 4);
            float4 vr = *(const float4*)(rp + q * 4);
            f[q * 4 + 0] = vf.x; f[q * 4 + 1] = vf.y; f[q * 4 + 2] = vf.z; f[q * 4 + 3] = vf.w;
            rn[q * 4 + 0] = vr.x; rn[q * 4 + 1] = vr.y; rn[q * 4 + 2] = vr.z; rn[q * 4 + 3] = vr.w;
        }
        float p = 0.f;
#pragma unroll
        for (int j = 0; j < 16; j++) p = fmaf(f[j], rn[j], p);
        // reduce across 8 lanes of this subgroup (xor 1,2,4 stays in subgroup)
        p += __shfl_xor_sync(0xffffffffu, p, 1);
        p += __shfl_xor_sync(0xffffffffu, p, 2);
        p += __shfl_xor_sync(0xffffffffu, p, 4);
        float wgt = __expf(tt[ed.y] - smax) * invs * act;
        float c = 2.f * p * wgt;
#pragma unroll
        for (int j = 0; j < 16; j++) acc[j] += wgt * f[j] - c * rn[j];
    }
    // cross-subgroup reduction (dims align across subs)
#pragma unroll
    for (int j = 0; j < 16; j++) {
        acc[j] += __shfl_xor_sync(0xffffffffu, acc[j], 8);
        acc[j] += __shfl_xor_sync(0xffffffffu, acc[j], 16);
    }
    if (sub == 0) {
        float* o = &g_out[dual][(size_t)w * FD + (layer + 1) * FF + l8 * 16];
#pragma unroll
        for (int j = 0; j < 16; j++) o[j] = tanhf(acc[j]);
    }
}

// ------------------------ proxy normalization -----------------------------------
__global__ void pnorm_kernel(const float* __restrict__ pe, const float* __restrict__ pr) {
    int w = (blockIdx.x * blockDim.x + threadIdx.x) >> 5;
    if (w >= 2 * PP) return;
    int lane = threadIdx.x & 31;
    int dual = (w >= PP) ? 1 : 0;
    int row = w & (PP - 1);
    const float* p = dual ? pr : pe;
    float v[12];
    float ss = 0;
#pragma unroll
    for (int j = 0; j < 12; j++) {
        v[j] = p[(size_t)row * FD + lane + 32 * j];
        ss += v[j] * v[j];
    }
    ss = wsum(ss);
    float inv = 1.f / fmaxf(sqrtf(ss), EPSV);
#pragma unroll
    for (int j = 0; j < 12; j++)
        g_pn[dual][(size_t)row * FD + lane + 32 * j] = v[j] * inv;
}

// ---------- S = l2norm(O) @ Pn^T, fused row-softmax -> g_att --------------------
__global__ void __launch_bounds__(256) s_kernel(int N_) {
    __shared__ float As[32][128];
    __shared__ float Bs[32][68];
    int dual = blockIdx.z;
    const float* A = g_out[dual];
    const float* B = g_pn[dual];
    int tid = threadIdx.x;
    int tx = tid & 15, ty = tid >> 4;
    int rowBase = blockIdx.x * 128;
    unsigned long long acc2[8][2];
    float ss[8];
#pragma unroll
    for (int i = 0; i < 8; i++) { acc2[i][0] = 0ull; acc2[i][1] = 0ull; ss[i] = 0.f; }

    for (int k0 = 0; k0 < FD; k0 += 32) {
#pragma unroll
        for (int ld = 0; ld < 4; ld++) {
            int slot = tid + 256 * ld;
            int r = slot >> 3, c4 = slot & 7;
            int grow = rowBase + r;
            float4 v = (grow < N_) ? *(const float4*)(A + (size_t)grow * FD + k0 + c4 * 4)
                                   : make_float4(0, 0, 0, 0);
            As[c4 * 4 + 0][r] = v.x;
            As[c4 * 4 + 1][r] = v.y;
            As[c4 * 4 + 2][r] = v.z;
            As[c4 * 4 + 3][r] = v.w;
        }
#pragma unroll
        for (int ld = 0; ld < 2; ld++) {
            int slot = tid + 256 * ld;
            int p = slot >> 3, c4 = slot & 7;
            float4 v = *(const float4*)(B + (size_t)p * FD + k0 + c4 * 4);
            Bs[c4 * 4 + 0][p] = v.x;
            Bs[c4 * 4 + 1][p] = v.y;
            Bs[c4 * 4 + 2][p] = v.z;
            Bs[c4 * 4 + 3][p] = v.w;
        }
        __syncthreads();
#pragma unroll
        for (int k = 0; k < 32; k++) {
            float ra[8];
            *(float4*)(&ra[0]) = *(const float4*)(&As[k][ty * 8]);
            *(float4*)(&ra[4]) = *(const float4*)(&As[k][ty * 8 + 4]);
            ulonglong2 b = *(const ulonglong2*)(&Bs[k][tx * 4]);
#pragma unroll
            for (int i = 0; i < 8; i++) {
                unsigned long long a2 = pack2(ra[i]);
                fma2(acc2[i][0], a2, b.x);
                fma2(acc2[i][1], a2, b.y);
                ss[i] = fmaf(ra[i], ra[i], ss[i]);
            }
        }
        __syncthreads();
    }
    // fused: scale by 1/||O_row||, softmax over the 64 proxies of each row.
    // Row (ty, i) lives on the 16 threads sharing ty (lanes (ty&1)*16 + tx).
    float* ATT = g_att[dual];
#pragma unroll
    for (int i = 0; i < 8; i++) {
        float inv = 1.f / fmaxf(sqrtf(ss[i]), EPSV);
        float v0 = lo32(acc2[i][0]) * inv;
        float v1 = hi32(acc2[i][0]) * inv;
        float v2 = lo32(acc2[i][1]) * inv;
        float v3 = hi32(acc2[i][1]) * inv;
        float m = fmaxf(fmaxf(v0, v1), fmaxf(v2, v3));
#pragma unroll
        for (int o = 8; o; o >>= 1) m = fmaxf(m, __shfl_xor_sync(0xffffffffu, m, o));
        float e0 = __expf(v0 - m), e1 = __expf(v1 - m);
        float e2 = __expf(v2 - m), e3 = __expf(v3 - m);
        float sm = e0 + e1 + e2 + e3;
#pragma unroll
        for (int o = 8; o; o >>= 1) sm += __shfl_xor_sync(0xffffffffu, sm, o);
        float r = 1.f / sm;
        int n = rowBase + ty * 8 + i;
        if (n < N_) {
            float* d = ATT + (size_t)n * PP + tx * 4;
            d[0] = e0 * r; d[1] = e1 * r; d[2] = e2 * r; d[3] = e3 * r;
        }
    }
}

// ------------------------ PF = O - Att @ P  [N,384] GEMM (K=64) -----------------
__global__ void __launch_bounds__(256) pf_kernel(const float* __restrict__ pe,
                                                 const float* __restrict__ pr, int N_) {
    __shared__ float As[32][128];
    __shared__ float Bs[32][128];
    int dual = blockIdx.z;
    const float* P = dual ? pr : pe;
    const float* A = g_att[dual];
    int tid = threadIdx.x;
    int tx = tid & 15, ty = tid >> 4;
    int rowBase = blockIdx.y * 128;
    int colBase = blockIdx.x * 128;
    unsigned long long acc2[8][4];
#pragma unroll
    for (int i = 0; i < 8; i++)
#pragma unroll
        for (int j = 0; j < 4; j++) acc2[i][j] = 0ull;

    for (int k0 = 0; k0 < PP; k0 += 32) {
#pragma unroll
        for (int ld = 0; ld < 4; ld++) {
            int slot = tid + 256 * ld;
            int r = slot >> 3, c4 = slot & 7;
            int grow = rowBase + r;
            float4 v = (grow < N_) ? *(const float4*)(A + (size_t)grow * PP + k0 + c4 * 4)
                                   : make_float4(0, 0, 0, 0);
            As[c4 * 4 + 0][r] = v.x;
            As[c4 * 4 + 1][r] = v.y;
            As[c4 * 4 + 2][r] = v.z;
            As[c4 * 4 + 3][r] = v.w;
        }
#pragma unroll
        for (int ld = 0; ld < 4; ld++) {
            int slot = tid + 256 * ld;
            int r = slot >> 5, c4 = slot & 31;
            float4 v = *(const float4*)(P + (size_t)(k0 + r) * FD + colBase + c4 * 4);
            *(float4*)(&Bs[r][c4 * 4]) = v;
        }
        __syncthreads();
#pragma unroll
        for (int k = 0; k < 32; k++) {
            float ra[8];
            *(float4*)(&ra[0]) = *(const float4*)(&As[k][ty * 8]);
            *(float4*)(&ra[4]) = *(const float4*)(&As[k][ty * 8 + 4]);
            ulonglong2 b0 = *(const ulonglong2*)(&Bs[k][tx * 8]);
            ulonglong2 b1 = *(const ulonglong2*)(&Bs[k][tx * 8 + 4]);
#pragma unroll
            for (int i = 0; i < 8; i++) {
                unsigned long long a2 = pack2(ra[i]);
                fma2(acc2[i][0], a2, b0.x);
                fma2(acc2[i][1], a2, b0.y);
                fma2(acc2[i][2], a2, b1.x);
                fma2(acc2[i][3], a2, b1.y);
            }
        }
        __syncthreads();
    }
    const float* O = g_out[dual];
    float* PF = g_pf[dual];
#pragma unroll
    for (int i = 0; i < 8; i++) {
        int n = rowBase + ty * 8 + i;
        if (n >= N_) continue;
        int c = colBase + tx * 8;
        const float* orow = O + (size_t)n * FD + c;
        float* d = PF + (size_t)n * FD + c;
        d[0] = orow[0] - lo32(acc2[i][0]);
        d[1] = orow[1] - hi32(acc2[i][0]);
        d[2] = orow[2] - lo32(acc2[i][1]);
        d[3] = orow[3] - hi32(acc2[i][1]);
        d[4] = orow[4] - lo32(acc2[i][2]);
        d[5] = orow[5] - hi32(acc2[i][2]);
        d[6] = orow[6] - lo32(acc2[i][3]);
        d[7] = orow[7] - hi32(acc2[i][3]);
    }
}

// ------------------------ F2: gate GEMM + final blend (BK=32) -------------------
__global__ void __launch_bounds__(256) f2_kernel(const float* __restrict__ We,
                                                 const float* __restrict__ Wr,
                                                 const float* __restrict__ be,
                                                 const float* __restrict__ br,
                                                 float* __restrict__ out, int N_) {
    __shared__ float As[32][128];
    __shared__ float Bs[32][128];
    int dual = blockIdx.z;
    const float* W = dual ? Wr : We;
    const float* bias = dual ? br : be;
    int tid = threadIdx.x;
    int tx = tid & 15, ty = tid >> 4;
    int rowBase = blockIdx.y * 128;
    int colBase = blockIdx.x * 128;
    const float* A = g_pf[dual];
    unsigned long long acc2[8][4];
#pragma unroll
    for (int i = 0; i < 8; i++)
#pragma unroll
        for (int j = 0; j < 4; j++) acc2[i][j] = 0ull;

    for (int k0 = 0; k0 < FD; k0 += 32) {
#pragma unroll
        for (int ld = 0; ld < 4; ld++) {
            int slot = tid + 256 * ld;
            int r = slot >> 3, c4 = slot & 7;
            int grow = rowBase + r;
            float4 v = (grow < N_) ? *(const float4*)(A + (size_t)grow * FD + k0 + c4 * 4)
                                   : make_float4(0, 0, 0, 0);
            As[c4 * 4 + 0][r] = v.x;
            As[c4 * 4 + 1][r] = v.y;
            As[c4 * 4 + 2][r] = v.z;
            As[c4 * 4 + 3][r] = v.w;
        }
#pragma unroll
        for (int ld = 0; ld < 4; ld++) {
            int slot = tid + 256 * ld;
            int r = slot >> 5, c4 = slot & 31;
            float4 v = *(const float4*)(W + (size_t)(k0 + r) * FD + colBase + c4 * 4);
            *(float4*)(&Bs[r][c4 * 4]) = v;
        }
        __syncthreads();
#pragma unroll
        for (int k = 0; k < 32; k++) {
            float ra[8];
            *(float4*)(&ra[0]) = *(const float4*)(&As[k][ty * 8]);
            *(float4*)(&ra[4]) = *(const float4*)(&As[k][ty * 8 + 4]);
            ulonglong2 b0 = *(const ulonglong2*)(&Bs[k][tx * 8]);
            ulonglong2 b1 = *(const ulonglong2*)(&Bs[k][tx * 8 + 4]);
#pragma unroll
            for (int i = 0; i < 8; i++) {
                unsigned long long a2 = pack2(ra[i]);
                fma2(acc2[i][0], a2, b0.x);
                fma2(acc2[i][1], a2, b0.y);
                fma2(acc2[i][2], a2, b1.x);
                fma2(acc2[i][3], a2, b1.y);
            }
        }
        __syncthreads();
    }

    const float* O = g_out[dual];
#pragma unroll
    for (int i = 0; i < 8; i++) {
        int n = rowBase + ty * 8 + i;
        if (n >= N_) continue;
        float accv[8];
        accv[0] = lo32(acc2[i][0]); accv[1] = hi32(acc2[i][0]);
        accv[2] = lo32(acc2[i][1]); accv[3] = hi32(acc2[i][1]);
        accv[4] = lo32(acc2[i][2]); accv[5] = hi32(acc2[i][2]);
        accv[6] = lo32(acc2[i][3]); accv[7] = hi32(acc2[i][3]);
#pragma unroll
        for (int j = 0; j < 8; j++) {
            int c = colBase + tx * 8 + j;
            float g = 1.f / (1.f + __expf(-(accv[j] + bias[c])));
            float o = O[(size_t)n * FD + c];
            float pf = A[(size_t)n * FD + c];
            out[(size_t)n * (2 * FD) + dual * FD + c] = g * o + (1.f - g) * pf;
        }
    }
}

// ------------------------ launch ------------------------------------------------
extern "C" void kernel_launch(void* const* d_in, const int* in_sizes, int n_in,
                              void* d_out, int out_size) {
    const float* ent_emb = (const float*)d_in[0];
    const float* rel_emb = (const float*)d_in[1];
    const int* edge_src  = (const int*)d_in[2];
    const int* edge_dst  = (const int*)d_in[3];
    const int* edge_rel  = (const int*)d_in[4];
    const float* attn_e  = (const float*)d_in[5];
    const float* gate_e  = (const float*)d_in[6];
    const float* proxy_e = (const float*)d_in[7];
    const float* bias_e  = (const float*)d_in[8];
    const float* attn_r  = (const float*)d_in[9];
    const float* gate_r  = (const float*)d_in[10];
    const float* proxy_r = (const float*)d_in[11];
    const float* bias_r  = (const float*)d_in[12];

    int N_ = in_sizes[0] / FF;
    int R_ = in_sizes[1] / FF;
    int E_ = in_sizes[2];
    float* out = (float*)d_out;

    zero_deg_kernel<<<(N_ + 255) / 256, 256>>>(N_);
    count_kernel<<<(E_ + 255) / 256, 256>>>(edge_dst, E_);
    scan_kernel<<<1, 1024>>>(N_);
    scatter_kernel<<<(E_ + 255) / 256, 256>>>(edge_dst, edge_src, edge_rel, E_);
    relnorm_kernel<<<(R_ * 32 + 255) / 256, 256>>>(rel_emb, attn_e, attn_r, R_);
    stats_kernel<<<1184, 256>>>(N_, R_);
    init_kernel<<<(N_ * 32 + 255) / 256, 256>>>(ent_emb, rel_emb, N_);

    int lgrid = (2 * N_ * 32 + 255) / 256;
    layer_kernel<<<lgrid, 256>>>(0, N_, R_);
    layer_kernel<<<lgrid, 256>>>(1, N_, R_);

    pnorm_kernel<<<16, 256>>>(proxy_e, proxy_r);

    dim3 gs((N_ + 127) / 128, 1, 2);
    s_kernel<<<gs, 256>>>(N_);

    dim3 gpf(FD / 128, (N_ + 127) / 128, 2);
    pf_kernel<<<gpf, 256>>>(proxy_e, proxy_r, N_);

    dim3 g2(FD / 128, (N_ + 127) / 128, 2);
    f2_kernel<<<g2, 256>>>(gate_e, gate_r, bias_e, bias_r, out, N_);
}

// round 5
// speedup vs baseline: 1.8268x; 1.8268x over previous
#include <cuda_runtime.h>
#include <math.h>

#define MAXN 50000
#define MAXE 800000
#define MAXR 2000
#define FF   128
#define FD   384
#define PP   64
#define EPSV 1e-12f

// ------------------------ scratch (device globals, no allocs) ------------------
__device__ int   g_deg[MAXN];
__device__ int   g_rowptr[MAXN + 1];
__device__ int   g_cursor[MAXN];
__device__ int2  g_edge[MAXE];                  // (src, rel) in CSR-by-dst order
__device__ float g_relnorm[MAXR * FF];
__device__ float g_ttab[4 * MAXR];
__device__ float g_smax[4 * MAXN];
__device__ float g_ssum[4 * MAXN];
__device__ float g_out[2][(size_t)MAXN * FD];
__device__ float g_pf[2][(size_t)MAXN * FD];
__device__ float g_pn[2][PP * FD];              // l2-normalized proxy rows
__device__ float g_att[2][(size_t)MAXN * PP];   // softmaxed attention

__device__ __forceinline__ float wsum(float v) {
#pragma unroll
    for (int o = 16; o; o >>= 1) v += __shfl_xor_sync(0xffffffffu, v, o);
    return v;
}
__device__ __forceinline__ float wmax(float v) {
#pragma unroll
    for (int o = 16; o; o >>= 1) v = fmaxf(v, __shfl_xor_sync(0xffffffffu, v, o));
    return v;
}

// ------------------------ packed f32x2 helpers ---------------------------------
__device__ __forceinline__ unsigned long long pack2(float x) {
    unsigned long long r;
    unsigned u = __float_as_uint(x);
    asm("mov.b64 %0, {%1, %1};" : "=l"(r) : "r"(u));
    return r;
}
__device__ __forceinline__ void fma2(unsigned long long& d, unsigned long long a,
                                     unsigned long long b) {
    asm("fma.rn.f32x2 %0, %1, %2, %0;" : "+l"(d) : "l"(a), "l"(b));
}
__device__ __forceinline__ float lo32(unsigned long long v) {
    return __uint_as_float((unsigned)v);
}
__device__ __forceinline__ float hi32(unsigned long long v) {
    return __uint_as_float((unsigned)(v >> 32));
}

// ------------------------ CSR build ------------------------
__global__ void zero_deg_kernel(int N_) {
    int i = blockIdx.x * blockDim.x + threadIdx.x;
    if (i < N_) g_deg[i] = 0;
}

__global__ void count_kernel(const int* __restrict__ edst, int E_) {
    int e = blockIdx.x * blockDim.x + threadIdx.x;
    if (e < E_) atomicAdd(&g_deg[edst[e]], 1);
}

__global__ void scan_kernel(int N_) {
    __shared__ int sh[1024];
    __shared__ int carry;
    if (threadIdx.x == 0) carry = 0;
    __syncthreads();
    for (int base = 0; base < N_; base += 1024) {
        int i = base + threadIdx.x;
        int v = (i < N_) ? g_deg[i] : 0;
        sh[threadIdx.x] = v;
        __syncthreads();
#pragma unroll
        for (int off = 1; off < 1024; off <<= 1) {
            int t = (threadIdx.x >= off) ? sh[threadIdx.x - off] : 0;
            __syncthreads();
            sh[threadIdx.x] += t;
            __syncthreads();
        }
        int inc = sh[threadIdx.x];
        int exc = inc - v + carry;
        if (i < N_) { g_rowptr[i] = exc; g_cursor[i] = exc; }
        __syncthreads();
        if (threadIdx.x == 1023) carry += sh[1023];
        __syncthreads();
    }
    if (threadIdx.x == 0) g_rowptr[N_] = carry;
}

__global__ void scatter_kernel(const int* __restrict__ edst,
                               const int* __restrict__ esrc,
                               const int* __restrict__ erel, int E_) {
    int e = blockIdx.x * blockDim.x + threadIdx.x;
    if (e < E_) {
        int p = atomicAdd(&g_cursor[edst[e]], 1);
        g_edge[p] = make_int2(esrc[e], erel[e]);
    }
}

// ------------------------ relation normalization + attn tables ------------------
__global__ void relnorm_kernel(const float* __restrict__ rel,
                               const float* __restrict__ attn_e,
                               const float* __restrict__ attn_r, int R_) {
    int w = (blockIdx.x * blockDim.x + threadIdx.x) >> 5;
    int lane = threadIdx.x & 31;
    if (w >= R_) return;
    float4 v = *(const float4*)(rel + (size_t)w * FF + lane * 4);
    float ss = v.x * v.x + v.y * v.y + v.z * v.z + v.w * v.w;
    ss = wsum(ss);
    float inv = 1.f / fmaxf(sqrtf(ss), EPSV);
    float4 rn = make_float4(v.x * inv, v.y * inv, v.z * inv, v.w * inv);
    *(float4*)(g_relnorm + (size_t)w * FF + lane * 4) = rn;

    float4 a0 = *(const float4*)(attn_e + lane * 4);
    float4 a1 = *(const float4*)(attn_e + FF + lane * 4);
    float4 a2 = *(const float4*)(attn_r + lane * 4);
    float4 a3 = *(const float4*)(attn_r + FF + lane * 4);
    float d0 = wsum(rn.x * a0.x + rn.y * a0.y + rn.z * a0.z + rn.w * a0.w);
    float d1 = wsum(rn.x * a1.x + rn.y * a1.y + rn.z * a1.z + rn.w * a1.w);
    float d2 = wsum(rn.x * a2.x + rn.y * a2.y + rn.z * a2.z + rn.w * a2.w);
    float d3 = wsum(rn.x * a3.x + rn.y * a3.y + rn.z * a3.z + rn.w * a3.w);
    if (lane == 0) {
        g_ttab[0 * R_ + w] = d0;
        g_ttab[1 * R_ + w] = d1;
        g_ttab[2 * R_ + w] = d2;
        g_ttab[3 * R_ + w] = d3;
    }
}

// ------------------------ edge-softmax stats (all 4 tables at once) -------------
__global__ void __launch_bounds__(256) stats_kernel(int N_, int R_) {
    __shared__ float tab[4 * MAXR];
    int tid = threadIdx.x;
    for (int i = tid; i < 4 * R_; i += blockDim.x) tab[i] = g_ttab[i];
    __syncthreads();
    int warp = tid >> 5, lane = tid & 31;
    for (int n = blockIdx.x * 8 + warp; n < N_; n += gridDim.x * 8) {
        int s = g_rowptr[n], e = g_rowptr[n + 1];
        float m0 = -1e30f, m1 = -1e30f, m2 = -1e30f, m3 = -1e30f;
        for (int i = s + lane; i < e; i += 32) {
            int r = g_edge[i].y;
            m0 = fmaxf(m0, tab[r]);
            m1 = fmaxf(m1, tab[R_ + r]);
            m2 = fmaxf(m2, tab[2 * R_ + r]);
            m3 = fmaxf(m3, tab[3 * R_ + r]);
        }
        m0 = wmax(m0); m1 = wmax(m1); m2 = wmax(m2); m3 = wmax(m3);
        float s0 = 0, s1 = 0, s2 = 0, s3 = 0;
        for (int i = s + lane; i < e; i += 32) {
            int r = g_edge[i].y;
            s0 += __expf(tab[r] - m0);
            s1 += __expf(tab[R_ + r] - m1);
            s2 += __expf(tab[2 * R_ + r] - m2);
            s3 += __expf(tab[3 * R_ + r] - m3);
        }
        s0 = wsum(s0); s1 = wsum(s1); s2 = wsum(s2); s3 = wsum(s3);
        if (lane == 0) {
            g_smax[0 * N_ + n] = m0; g_ssum[0 * N_ + n] = s0;
            g_smax[1 * N_ + n] = m1; g_ssum[1 * N_ + n] = s1;
            g_smax[2 * N_ + n] = m2; g_ssum[2 * N_ + n] = s2;
            g_smax[3 * N_ + n] = m3; g_ssum[3 * N_ + n] = s3;
        }
    }
}

// ---------- initial mean features: 1 warp/node, lane=float4, 2-edge ILP ---------
__global__ void __launch_bounds__(256) init_kernel(const float* __restrict__ ent,
                                                   const float* __restrict__ rel, int N_) {
    int w = (blockIdx.x * blockDim.x + threadIdx.x) >> 5;
    if (w >= N_) return;
    int lane = threadIdx.x & 31;
    int s = g_rowptr[w], e = g_rowptr[w + 1];
    float4 ae = make_float4(0, 0, 0, 0), ar = make_float4(0, 0, 0, 0);
    int i = s;
    for (; i + 1 < e; i += 2) {
        int2 e0 = g_edge[i], e1 = g_edge[i + 1];
        float4 a = *(const float4*)(ent + (size_t)e0.x * FF + lane * 4);
        float4 b = *(const float4*)(rel + (size_t)e0.y * FF + lane * 4);
        float4 c = *(const float4*)(ent + (size_t)e1.x * FF + lane * 4);
        float4 d = *(const float4*)(rel + (size_t)e1.y * FF + lane * 4);
        ae.x += a.x + c.x; ae.y += a.y + c.y; ae.z += a.z + c.z; ae.w += a.w + c.w;
        ar.x += b.x + d.x; ar.y += b.y + d.y; ar.z += b.z + d.z; ar.w += b.w + d.w;
    }
    if (i < e) {
        int2 e0 = g_edge[i];
        float4 a = *(const float4*)(ent + (size_t)e0.x * FF + lane * 4);
        float4 b = *(const float4*)(rel + (size_t)e0.y * FF + lane * 4);
        ae.x += a.x; ae.y += a.y; ae.z += a.z; ae.w += a.w;
        ar.x += b.x; ar.y += b.y; ar.z += b.z; ar.w += b.w;
    }
    float inv = 1.f / fmaxf((float)(e - s), 1.f);
    float* oe = &g_out[0][(size_t)w * FD + lane * 4];
    float* orr = &g_out[1][(size_t)w * FD + lane * 4];
    oe[0] = tanhf(ae.x * inv); oe[1] = tanhf(ae.y * inv);
    oe[2] = tanhf(ae.z * inv); oe[3] = tanhf(ae.w * inv);
    orr[0] = tanhf(ar.x * inv); orr[1] = tanhf(ar.y * inv);
    orr[2] = tanhf(ar.z * inv); orr[3] = tanhf(ar.w * inv);
}

// ---------- GNN layer: 1 warp/node, lane=float4 (coalesced), 4-edge ILP ---------
__global__ void __launch_bounds__(256) layer_kernel(int layer, int N_, int R_) {
    int gw = (blockIdx.x * blockDim.x + threadIdx.x) >> 5;
    if (gw >= 2 * N_) return;
    int dual = gw >= N_;
    int w = gw - dual * N_;
    int lane = threadIdx.x & 31;
    int s = g_rowptr[w], e = g_rowptr[w + 1];
    int t = dual * 2 + layer;
    const float* feats = g_out[dual];
    const float* tt = g_ttab + (size_t)t * R_;
    float smax = g_smax[(size_t)t * N_ + w];
    float invs = (e > s) ? 1.f / g_ssum[(size_t)t * N_ + w] : 0.f;
    int coff = layer * FF + lane * 4;
    float4 acc = make_float4(0, 0, 0, 0);

    for (int i = s; i < e; i += 4) {
        int i1 = min(i + 1, e - 1), i2 = min(i + 2, e - 1), i3 = min(i + 3, e - 1);
        float a1 = (i + 1 < e) ? 1.f : 0.f;
        float a2 = (i + 2 < e) ? 1.f : 0.f;
        float a3 = (i + 3 < e) ? 1.f : 0.f;
        int2 e0 = g_edge[i], e1 = g_edge[i1], e2 = g_edge[i2], e3 = g_edge[i3];
        float4 f0 = *(const float4*)(feats + (size_t)e0.x * FD + coff);
        float4 f1 = *(const float4*)(feats + (size_t)e1.x * FD + coff);
        float4 f2 = *(const float4*)(feats + (size_t)e2.x * FD + coff);
        float4 f3 = *(const float4*)(feats + (size_t)e3.x * FD + coff);
        float4 r0 = *(const float4*)(g_relnorm + (size_t)e0.y * FF + lane * 4);
        float4 r1 = *(const float4*)(g_relnorm + (size_t)e1.y * FF + lane * 4);
        float4 r2 = *(const float4*)(g_relnorm + (size_t)e2.y * FF + lane * 4);
        float4 r3 = *(const float4*)(g_relnorm + (size_t)e3.y * FF + lane * 4);
        float p0 = f0.x * r0.x + f0.y * r0.y + f0.z * r0.z + f0.w * r0.w;
        float p1 = f1.x * r1.x + f1.y * r1.y + f1.z * r1.z + f1.w * r1.w;
        float p2 = f2.x * r2.x + f2.y * r2.y + f2.z * r2.z + f2.w * r2.w;
        float p3 = f3.x * r3.x + f3.y * r3.y + f3.z * r3.z + f3.w * r3.w;
        // four independent butterfly chains — overlap in the pipeline
#pragma unroll
        for (int o = 16; o; o >>= 1) {
            p0 += __shfl_xor_sync(0xffffffffu, p0, o);
            p1 += __shfl_xor_sync(0xffffffffu, p1, o);
            p2 += __shfl_xor_sync(0xffffffffu, p2, o);
            p3 += __shfl_xor_sync(0xffffffffu, p3, o);
        }
        float w0 = __expf(tt[e0.y] - smax) * invs;
        float w1 = __expf(tt[e1.y] - smax) * invs * a1;
        float w2 = __expf(tt[e2.y] - smax) * invs * a2;
        float w3 = __expf(tt[e3.y] - smax) * invs * a3;
        float c0 = 2.f * p0 * w0, c1 = 2.f * p1 * w1;
        float c2 = 2.f * p2 * w2, c3 = 2.f * p3 * w3;
        acc.x += w0 * f0.x - c0 * r0.x + w1 * f1.x - c1 * r1.x
               + w2 * f2.x - c2 * r2.x + w3 * f3.x - c3 * r3.x;
        acc.y += w0 * f0.y - c0 * r0.y + w1 * f1.y - c1 * r1.y
               + w2 * f2.y - c2 * r2.y + w3 * f3.y - c3 * r3.y;
        acc.z += w0 * f0.z - c0 * r0.z + w1 * f1.z - c1 * r1.z
               + w2 * f2.z - c2 * r2.z + w3 * f3.z - c3 * r3.z;
        acc.w += w0 * f0.w - c0 * r0.w + w1 * f1.w - c1 * r1.w
               + w2 * f2.w - c2 * r2.w + w3 * f3.w - c3 * r3.w;
    }
    float* o = &g_out[dual][(size_t)w * FD + (layer + 1) * FF + lane * 4];
    o[0] = tanhf(acc.x); o[1] = tanhf(acc.y);
    o[2] = tanhf(acc.z); o[3] = tanhf(acc.w);
}

// ------------------------ proxy normalization -----------------------------------
__global__ void pnorm_kernel(const float* __restrict__ pe, const float* __restrict__ pr) {
    int w = (blockIdx.x * blockDim.x + threadIdx.x) >> 5;
    if (w >= 2 * PP) return;
    int lane = threadIdx.x & 31;
    int dual = (w >= PP) ? 1 : 0;
    int row = w & (PP - 1);
    const float* p = dual ? pr : pe;
    float v[12];
    float ss = 0;
#pragma unroll
    for (int j = 0; j < 12; j++) {
        v[j] = p[(size_t)row * FD + lane + 32 * j];
        ss += v[j] * v[j];
    }
    ss = wsum(ss);
    float inv = 1.f / fmaxf(sqrtf(ss), EPSV);
#pragma unroll
    for (int j = 0; j < 12; j++)
        g_pn[dual][(size_t)row * FD + lane + 32 * j] = v[j] * inv;
}

// ---------- S = l2norm(O) @ Pn^T, fused row-softmax -> g_att --------------------
__global__ void __launch_bounds__(256) s_kernel(int N_) {
    __shared__ float As[32][128];
    __shared__ float Bs[32][68];
    int dual = blockIdx.z;
    const float* A = g_out[dual];
    const float* B = g_pn[dual];
    int tid = threadIdx.x;
    int tx = tid & 15, ty = tid >> 4;
    int rowBase = blockIdx.x * 128;
    unsigned long long acc2[8][2];
    float ss[8];
#pragma unroll
    for (int i = 0; i < 8; i++) { acc2[i][0] = 0ull; acc2[i][1] = 0ull; ss[i] = 0.f; }

    for (int k0 = 0; k0 < FD; k0 += 32) {
#pragma unroll
        for (int ld = 0; ld < 4; ld++) {
            int slot = tid + 256 * ld;
            int r = slot >> 3, c4 = slot & 7;
            int grow = rowBase + r;
            float4 v = (grow < N_) ? *(const float4*)(A + (size_t)grow * FD + k0 + c4 * 4)
                                   : make_float4(0, 0, 0, 0);
            As[c4 * 4 + 0][r] = v.x;
            As[c4 * 4 + 1][r] = v.y;
            As[c4 * 4 + 2][r] = v.z;
            As[c4 * 4 + 3][r] = v.w;
        }
#pragma unroll
        for (int ld = 0; ld < 2; ld++) {
            int slot = tid + 256 * ld;
            int p = slot >> 3, c4 = slot & 7;
            float4 v = *(const float4*)(B + (size_t)p * FD + k0 + c4 * 4);
            Bs[c4 * 4 + 0][p] = v.x;
            Bs[c4 * 4 + 1][p] = v.y;
            Bs[c4 * 4 + 2][p] = v.z;
            Bs[c4 * 4 + 3][p] = v.w;
        }
        __syncthreads();
#pragma unroll
        for (int k = 0; k < 32; k++) {
            float ra[8];
            *(float4*)(&ra[0]) = *(const float4*)(&As[k][ty * 8]);
            *(float4*)(&ra[4]) = *(const float4*)(&As[k][ty * 8 + 4]);
            ulonglong2 b = *(const ulonglong2*)(&Bs[k][tx * 4]);
#pragma unroll
            for (int i = 0; i < 8; i++) {
                unsigned long long a2 = pack2(ra[i]);
                fma2(acc2[i][0], a2, b.x);
                fma2(acc2[i][1], a2, b.y);
                ss[i] = fmaf(ra[i], ra[i], ss[i]);
            }
        }
        __syncthreads();
    }
    float* ATT = g_att[dual];
#pragma unroll
    for (int i = 0; i < 8; i++) {
        float inv = 1.f / fmaxf(sqrtf(ss[i]), EPSV);
        float v0 = lo32(acc2[i][0]) * inv;
        float v1 = hi32(acc2[i][0]) * inv;
        float v2 = lo32(acc2[i][1]) * inv;
        float v3 = hi32(acc2[i][1]) * inv;
        float m = fmaxf(fmaxf(v0, v1), fmaxf(v2, v3));
#pragma unroll
        for (int o = 8; o; o >>= 1) m = fmaxf(m, __shfl_xor_sync(0xffffffffu, m, o));
        float e0 = __expf(v0 - m), e1 = __expf(v1 - m);
        float e2 = __expf(v2 - m), e3 = __expf(v3 - m);
        float sm = e0 + e1 + e2 + e3;
#pragma unroll
        for (int o = 8; o; o >>= 1) sm += __shfl_xor_sync(0xffffffffu, sm, o);
        float r = 1.f / sm;
        int n = rowBase + ty * 8 + i;
        if (n < N_) {
            float* d = ATT + (size_t)n * PP + tx * 4;
            d[0] = e0 * r; d[1] = e1 * r; d[2] = e2 * r; d[3] = e3 * r;
        }
    }
}

// ------------------------ PF = O - Att @ P  [N,384] GEMM (K=64) -----------------
__global__ void __launch_bounds__(256) pf_kernel(const float* __restrict__ pe,
                                                 const float* __restrict__ pr, int N_) {
    __shared__ float As[32][128];
    __shared__ float Bs[32][128];
    int dual = blockIdx.z;
    const float* P = dual ? pr : pe;
    const float* A = g_att[dual];
    int tid = threadIdx.x;
    int tx = tid & 15, ty = tid >> 4;
    int rowBase = blockIdx.y * 128;
    int colBase = blockIdx.x * 128;
    unsigned long long acc2[8][4];
#pragma unroll
    for (int i = 0; i < 8; i++)
#pragma unroll
        for (int j = 0; j < 4; j++) acc2[i][j] = 0ull;

    for (int k0 = 0; k0 < PP; k0 += 32) {
#pragma unroll
        for (int ld = 0; ld < 4; ld++) {
            int slot = tid + 256 * ld;
            int r = slot >> 3, c4 = slot & 7;
            int grow = rowBase + r;
            float4 v = (grow < N_) ? *(const float4*)(A + (size_t)grow * PP + k0 + c4 * 4)
                                   : make_float4(0, 0, 0, 0);
            As[c4 * 4 + 0][r] = v.x;
            As[c4 * 4 + 1][r] = v.y;
            As[c4 * 4 + 2][r] = v.z;
            As[c4 * 4 + 3][r] = v.w;
        }
#pragma unroll
        for (int ld = 0; ld < 4; ld++) {
            int slot = tid + 256 * ld;
            int r = slot >> 5, c4 = slot & 31;
            float4 v = *(const float4*)(P + (size_t)(k0 + r) * FD + colBase + c4 * 4);
            *(float4*)(&Bs[r][c4 * 4]) = v;
        }
        __syncthreads();
#pragma unroll
        for (int k = 0; k < 32; k++) {
            float ra[8];
            *(float4*)(&ra[0]) = *(const float4*)(&As[k][ty * 8]);
            *(float4*)(&ra[4]) = *(const float4*)(&As[k][ty * 8 + 4]);
            ulonglong2 b0 = *(const ulonglong2*)(&Bs[k][tx * 8]);
            ulonglong2 b1 = *(const ulonglong2*)(&Bs[k][tx * 8 + 4]);
#pragma unroll
            for (int i = 0; i < 8; i++) {
                unsigned long long a2 = pack2(ra[i]);
                fma2(acc2[i][0], a2, b0.x);
                fma2(acc2[i][1], a2, b0.y);
                fma2(acc2[i][2], a2, b1.x);
                fma2(acc2[i][3], a2, b1.y);
            }
        }
        __syncthreads();
    }
    const float* O = g_out[dual];
    float* PF = g_pf[dual];
#pragma unroll
    for (int i = 0; i < 8; i++) {
        int n = rowBase + ty * 8 + i;
        if (n >= N_) continue;
        int c = colBase + tx * 8;
        const float* orow = O + (size_t)n * FD + c;
        float* d = PF + (size_t)n * FD + c;
        d[0] = orow[0] - lo32(acc2[i][0]);
        d[1] = orow[1] - hi32(acc2[i][0]);
        d[2] = orow[2] - lo32(acc2[i][1]);
        d[3] = orow[3] - hi32(acc2[i][1]);
        d[4] = orow[4] - lo32(acc2[i][2]);
        d[5] = orow[5] - hi32(acc2[i][2]);
        d[6] = orow[6] - lo32(acc2[i][3]);
        d[7] = orow[7] - hi32(acc2[i][3]);
    }
}

// ------------------------ F2: gate GEMM + final blend (BK=32) -------------------
__global__ void __launch_bounds__(256) f2_kernel(const float* __restrict__ We,
                                                 const float* __restrict__ Wr,
                                                 const float* __restrict__ be,
                                                 const float* __restrict__ br,
                                                 float* __restrict__ out, int N_) {
    __shared__ float As[32][128];
    __shared__ float Bs[32][128];
    int dual = blockIdx.z;
    const float* W = dual ? Wr : We;
    const float* bias = dual ? br : be;
    int tid = threadIdx.x;
    int tx = tid & 15, ty = tid >> 4;
    int rowBase = blockIdx.y * 128;
    int colBase = blockIdx.x * 128;
    const float* A = g_pf[dual];
    unsigned long long acc2[8][4];
#pragma unroll
    for (int i = 0; i < 8; i++)
#pragma unroll
        for (int j = 0; j < 4; j++) acc2[i][j] = 0ull;

    for (int k0 = 0; k0 < FD; k0 += 32) {
#pragma unroll
        for (int ld = 0; ld < 4; ld++) {
            int slot = tid + 256 * ld;
            int r = slot >> 3, c4 = slot & 7;
            int grow = rowBase + r;
            float4 v = (grow < N_) ? *(const float4*)(A + (size_t)grow * FD + k0 + c4 * 4)
                                   : make_float4(0, 0, 0, 0);
            As[c4 * 4 + 0][r] = v.x;
            As[c4 * 4 + 1][r] = v.y;
            As[c4 * 4 + 2][r] = v.z;
            As[c4 * 4 + 3][r] = v.w;
        }
#pragma unroll
        for (int ld = 0; ld < 4; ld++) {
            int slot = tid + 256 * ld;
            int r = slot >> 5, c4 = slot & 31;
            float4 v = *(const float4*)(W + (size_t)(k0 + r) * FD + colBase + c4 * 4);
            *(float4*)(&Bs[r][c4 * 4]) = v;
        }
        __syncthreads();
#pragma unroll
        for (int k = 0; k < 32; k++) {
            float ra[8];
            *(float4*)(&ra[0]) = *(const float4*)(&As[k][ty * 8]);
            *(float4*)(&ra[4]) = *(const float4*)(&As[k][ty * 8 + 4]);
            ulonglong2 b0 = *(const ulonglong2*)(&Bs[k][tx * 8]);
            ulonglong2 b1 = *(const ulonglong2*)(&Bs[k][tx * 8 + 4]);
#pragma unroll
            for (int i = 0; i < 8; i++) {
                unsigned long long a2 = pack2(ra[i]);
                fma2(acc2[i][0], a2, b0.x);
                fma2(acc2[i][1], a2, b0.y);
                fma2(acc2[i][2], a2, b1.x);
                fma2(acc2[i][3], a2, b1.y);
            }
        }
        __syncthreads();
    }

    const float* O = g_out[dual];
#pragma unroll
    for (int i = 0; i < 8; i++) {
        int n = rowBase + ty * 8 + i;
        if (n >= N_) continue;
        float accv[8];
        accv[0] = lo32(acc2[i][0]); accv[1] = hi32(acc2[i][0]);
        accv[2] = lo32(acc2[i][1]); accv[3] = hi32(acc2[i][1]);
        accv[4] = lo32(acc2[i][2]); accv[5] = hi32(acc2[i][2]);
        accv[6] = lo32(acc2[i][3]); accv[7] = hi32(acc2[i][3]);
#pragma unroll
        for (int j = 0; j < 8; j++) {
            int c = colBase + tx * 8 + j;
            float g = 1.f / (1.f + __expf(-(accv[j] + bias[c])));
            float o = O[(size_t)n * FD + c];
            float pf = A[(size_t)n * FD + c];
            out[(size_t)n * (2 * FD) + dual * FD + c] = g * o + (1.f - g) * pf;
        }
    }
}

// ------------------------ launch ------------------------------------------------
extern "C" void kernel_launch(void* const* d_in, const int* in_sizes, int n_in,
                              void* d_out, int out_size) {
    const float* ent_emb = (const float*)d_in[0];
    const float* rel_emb = (const float*)d_in[1];
    const int* edge_src  = (const int*)d_in[2];
    const int* edge_dst  = (const int*)d_in[3];
    const int* edge_rel  = (const int*)d_in[4];
    const float* attn_e  = (const float*)d_in[5];
    const float* gate_e  = (const float*)d_in[6];
    const float* proxy_e = (const float*)d_in[7];
    const float* bias_e  = (const float*)d_in[8];
    const float* attn_r  = (const float*)d_in[9];
    const float* gate_r  = (const float*)d_in[10];
    const float* proxy_r = (const float*)d_in[11];
    const float* bias_r  = (const float*)d_in[12];

    int N_ = in_sizes[0] / FF;
    int R_ = in_sizes[1] / FF;
    int E_ = in_sizes[2];
    float* out = (float*)d_out;

    zero_deg_kernel<<<(N_ + 255) / 256, 256>>>(N_);
    count_kernel<<<(E_ + 255) / 256, 256>>>(edge_dst, E_);
    scan_kernel<<<1, 1024>>>(N_);
    scatter_kernel<<<(E_ + 255) / 256, 256>>>(edge_dst, edge_src, edge_rel, E_);
    relnorm_kernel<<<(R_ * 32 + 255) / 256, 256>>>(rel_emb, attn_e, attn_r, R_);
    stats_kernel<<<1184, 256>>>(N_, R_);
    init_kernel<<<(N_ * 32 + 255) / 256, 256>>>(ent_emb, rel_emb, N_);

    int lgrid = (2 * N_ * 32 + 255) / 256;
    layer_kernel<<<lgrid, 256>>>(0, N_, R_);
    layer_kernel<<<lgrid, 256>>>(1, N_, R_);

    pnorm_kernel<<<16, 256>>>(proxy_e, proxy_r);

    dim3 gs((N_ + 127) / 128, 1, 2);
    s_kernel<<<gs, 256>>>(N_);

    dim3 gpf(FD / 128, (N_ + 127) / 128, 2);
    pf_kernel<<<gpf, 256>>>(proxy_e, proxy_r, N_);

    dim3 g2(FD / 128, (N_ + 127) / 128, 2);
    f2_kernel<<<g2, 256>>>(gate_e, gate_r, bias_e, bias_r, out, N_);
}

// round 9
// speedup vs baseline: 2.0584x; 1.1267x over previous
#include <cuda_runtime.h>
#include <cuda_bf16.h>
#include <mma.h>
#include <stdint.h>
#include <math.h>

using namespace nvcuda;

#define MAXN 50000
#define MAXE 800000
#define MAXR 2000
#define FF   128
#define FD   384
#define PP   64
#define EPSV 1e-12f

// ------------------------ scratch (device globals, no allocs) ------------------
__device__ int   g_deg[MAXN];
__device__ int   g_rowptr[MAXN + 1];
__device__ int   g_cursor[MAXN];
__device__ int2  g_edge[MAXE];                  // (src, rel) in CSR-by-dst order
__device__ float g_relnorm[MAXR * FF];
__device__ float g_ttab[4 * MAXR];
__device__ float g_smax[4 * MAXN];
__device__ float g_ssum[4 * MAXN];
__device__ float g_out[2][(size_t)MAXN * FD];
__device__ float g_pn[2][PP * FD];              // l2-normalized proxy rows
__device__ float g_att[2][(size_t)MAXN * PP];   // softmaxed attention
__device__ __nv_bfloat16 g_pfh[2][(size_t)MAXN * FD];  // proxy_feature hi
__device__ __nv_bfloat16 g_pfl[2][(size_t)MAXN * FD];  // proxy_feature lo
__device__ __nv_bfloat16 g_wh[2][FD * FD];             // gate kernel hi
__device__ __nv_bfloat16 g_wl[2][FD * FD];             // gate kernel lo

__device__ __forceinline__ float wsum(float v) {
#pragma unroll
    for (int o = 16; o; o >>= 1) v += __shfl_xor_sync(0xffffffffu, v, o);
    return v;
}
__device__ __forceinline__ float wmax(float v) {
#pragma unroll
    for (int o = 16; o; o >>= 1) v = fmaxf(v, __shfl_xor_sync(0xffffffffu, v, o));
    return v;
}

// ------------------------ packed f32x2 helpers ---------------------------------
__device__ __forceinline__ unsigned long long pack2(float x) {
    unsigned long long r;
    unsigned u = __float_as_uint(x);
    asm("mov.b64 %0, {%1, %1};" : "=l"(r) : "r"(u));
    return r;
}
__device__ __forceinline__ void fma2(unsigned long long& d, unsigned long long a,
                                     unsigned long long b) {
    asm("fma.rn.f32x2 %0, %1, %2, %0;" : "+l"(d) : "l"(a), "l"(b));
}
__device__ __forceinline__ float lo32(unsigned long long v) {
    return __uint_as_float((unsigned)v);
}
__device__ __forceinline__ float hi32(unsigned long long v) {
    return __uint_as_float((unsigned)(v >> 32));
}

// ------------------------ CSR build ------------------------
__global__ void zero_deg_kernel(int N_) {
    int i = blockIdx.x * blockDim.x + threadIdx.x;
    if (i < N_) g_deg[i] = 0;
}

__global__ void count_kernel(const int* __restrict__ edst, int E_) {
    int e = blockIdx.x * blockDim.x + threadIdx.x;
    if (e < E_) atomicAdd(&g_deg[edst[e]], 1);
}

__global__ void scan_kernel(int N_) {
    __shared__ int sh[1024];
    __shared__ int carry;
    if (threadIdx.x == 0) carry = 0;
    __syncthreads();
    for (int base = 0; base < N_; base += 1024) {
        int i = base + threadIdx.x;
        int v = (i < N_) ? g_deg[i] : 0;
        sh[threadIdx.x] = v;
        __syncthreads();
#pragma unroll
        for (int off = 1; off < 1024; off <<= 1) {
            int t = (threadIdx.x >= off) ? sh[threadIdx.x - off] : 0;
            __syncthreads();
            sh[threadIdx.x] += t;
            __syncthreads();
        }
        int inc = sh[threadIdx.x];
        int exc = inc - v + carry;
        if (i < N_) { g_rowptr[i] = exc; g_cursor[i] = exc; }
        __syncthreads();
        if (threadIdx.x == 1023) carry += sh[1023];
        __syncthreads();
    }
    if (threadIdx.x == 0) g_rowptr[N_] = carry;
}

__global__ void scatter_kernel(const int* __restrict__ edst,
                               const int* __restrict__ esrc,
                               const int* __restrict__ erel, int E_) {
    int e = blockIdx.x * blockDim.x + threadIdx.x;
    if (e < E_) {
        int p = atomicAdd(&g_cursor[edst[e]], 1);
        g_edge[p] = make_int2(esrc[e], erel[e]);
    }
}

// ------------------------ relation normalization + attn tables ------------------
__global__ void relnorm_kernel(const float* __restrict__ rel,
                               const float* __restrict__ attn_e,
                               const float* __restrict__ attn_r, int R_) {
    int w = (blockIdx.x * blockDim.x + threadIdx.x) >> 5;
    int lane = threadIdx.x & 31;
    if (w >= R_) return;
    float4 v = *(const float4*)(rel + (size_t)w * FF + lane * 4);
    float ss = v.x * v.x + v.y * v.y + v.z * v.z + v.w * v.w;
    ss = wsum(ss);
    float inv = 1.f / fmaxf(sqrtf(ss), EPSV);
    float4 rn = make_float4(v.x * inv, v.y * inv, v.z * inv, v.w * inv);
    *(float4*)(g_relnorm + (size_t)w * FF + lane * 4) = rn;

    float4 a0 = *(const float4*)(attn_e + lane * 4);
    float4 a1 = *(const float4*)(attn_e + FF + lane * 4);
    float4 a2 = *(const float4*)(attn_r + lane * 4);
    float4 a3 = *(const float4*)(attn_r + FF + lane * 4);
    float d0 = wsum(rn.x * a0.x + rn.y * a0.y + rn.z * a0.z + rn.w * a0.w);
    float d1 = wsum(rn.x * a1.x + rn.y * a1.y + rn.z * a1.z + rn.w * a1.w);
    float d2 = wsum(rn.x * a2.x + rn.y * a2.y + rn.z * a2.z + rn.w * a2.w);
    float d3 = wsum(rn.x * a3.x + rn.y * a3.y + rn.z * a3.z + rn.w * a3.w);
    if (lane == 0) {
        g_ttab[0 * R_ + w] = d0;
        g_ttab[1 * R_ + w] = d1;
        g_ttab[2 * R_ + w] = d2;
        g_ttab[3 * R_ + w] = d3;
    }
}

// ------------------------ edge-softmax stats (all 4 tables at once) -------------
__global__ void __launch_bounds__(256) stats_kernel(int N_, int R_) {
    __shared__ float tab[4 * MAXR];
    int tid = threadIdx.x;
    for (int i = tid; i < 4 * R_; i += blockDim.x) tab[i] = g_ttab[i];
    __syncthreads();
    int warp = tid >> 5, lane = tid & 31;
    for (int n = blockIdx.x * 8 + warp; n < N_; n += gridDim.x * 8) {
        int s = g_rowptr[n], e = g_rowptr[n + 1];
        float m0 = -1e30f, m1 = -1e30f, m2 = -1e30f, m3 = -1e30f;
        for (int i = s + lane; i < e; i += 32) {
            int r = g_edge[i].y;
            m0 = fmaxf(m0, tab[r]);
            m1 = fmaxf(m1, tab[R_ + r]);
            m2 = fmaxf(m2, tab[2 * R_ + r]);
            m3 = fmaxf(m3, tab[3 * R_ + r]);
        }
        m0 = wmax(m0); m1 = wmax(m1); m2 = wmax(m2); m3 = wmax(m3);
        float s0 = 0, s1 = 0, s2 = 0, s3 = 0;
        for (int i = s + lane; i < e; i += 32) {
            int r = g_edge[i].y;
            s0 += __expf(tab[r] - m0);
            s1 += __expf(tab[R_ + r] - m1);
            s2 += __expf(tab[2 * R_ + r] - m2);
            s3 += __expf(tab[3 * R_ + r] - m3);
        }
        s0 = wsum(s0); s1 = wsum(s1); s2 = wsum(s2); s3 = wsum(s3);
        if (lane == 0) {
            g_smax[0 * N_ + n] = m0; g_ssum[0 * N_ + n] = s0;
            g_smax[1 * N_ + n] = m1; g_ssum[1 * N_ + n] = s1;
            g_smax[2 * N_ + n] = m2; g_ssum[2 * N_ + n] = s2;
            g_smax[3 * N_ + n] = m3; g_ssum[3 * N_ + n] = s3;
        }
    }
}

// ---------- initial mean features: 1 warp/node, lane=float4, 2-edge ILP ---------
__global__ void __launch_bounds__(256) init_kernel(const float* __restrict__ ent,
                                                   const float* __restrict__ rel, int N_) {
    int w = (blockIdx.x * blockDim.x + threadIdx.x) >> 5;
    if (w >= N_) return;
    int lane = threadIdx.x & 31;
    int s = g_rowptr[w], e = g_rowptr[w + 1];
    float4 ae = make_float4(0, 0, 0, 0), ar = make_float4(0, 0, 0, 0);
    int i = s;
    for (; i + 1 < e; i += 2) {
        int2 e0 = g_edge[i], e1 = g_edge[i + 1];
        float4 a = *(const float4*)(ent + (size_t)e0.x * FF + lane * 4);
        float4 b = *(const float4*)(rel + (size_t)e0.y * FF + lane * 4);
        float4 c = *(const float4*)(ent + (size_t)e1.x * FF + lane * 4);
        float4 d = *(const float4*)(rel + (size_t)e1.y * FF + lane * 4);
        ae.x += a.x + c.x; ae.y += a.y + c.y; ae.z += a.z + c.z; ae.w += a.w + c.w;
        ar.x += b.x + d.x; ar.y += b.y + d.y; ar.z += b.z + d.z; ar.w += b.w + d.w;
    }
    if (i < e) {
        int2 e0 = g_edge[i];
        float4 a = *(const float4*)(ent + (size_t)e0.x * FF + lane * 4);
        float4 b = *(const float4*)(rel + (size_t)e0.y * FF + lane * 4);
        ae.x += a.x; ae.y += a.y; ae.z += a.z; ae.w += a.w;
        ar.x += b.x; ar.y += b.y; ar.z += b.z; ar.w += b.w;
    }
    float inv = 1.f / fmaxf((float)(e - s), 1.f);
    float* oe = &g_out[0][(size_t)w * FD + lane * 4];
    float* orr = &g_out[1][(size_t)w * FD + lane * 4];
    oe[0] = tanhf(ae.x * inv); oe[1] = tanhf(ae.y * inv);
    oe[2] = tanhf(ae.z * inv); oe[3] = tanhf(ae.w * inv);
    orr[0] = tanhf(ar.x * inv); orr[1] = tanhf(ar.y * inv);
    orr[2] = tanhf(ar.z * inv); orr[3] = tanhf(ar.w * inv);
}

// ---------- GNN layer: 1 warp/node, lane=float4 (coalesced), 4-edge ILP ---------
__global__ void __launch_bounds__(256) layer_kernel(int layer, int N_, int R_) {
    int gw = (blockIdx.x * blockDim.x + threadIdx.x) >> 5;
    if (gw >= 2 * N_) return;
    int dual = gw >= N_;
    int w = gw - dual * N_;
    int lane = threadIdx.x & 31;
    int s = g_rowptr[w], e = g_rowptr[w + 1];
    int t = dual * 2 + layer;
    const float* feats = g_out[dual];
    const float* tt = g_ttab + (size_t)t * R_;
    float smax = g_smax[(size_t)t * N_ + w];
    float invs = (e > s) ? 1.f / g_ssum[(size_t)t * N_ + w] : 0.f;
    int coff = layer * FF + lane * 4;
    float4 acc = make_float4(0, 0, 0, 0);

    for (int i = s; i < e; i += 4) {
        int i1 = min(i + 1, e - 1), i2 = min(i + 2, e - 1), i3 = min(i + 3, e - 1);
        float a1 = (i + 1 < e) ? 1.f : 0.f;
        float a2 = (i + 2 < e) ? 1.f : 0.f;
        float a3 = (i + 3 < e) ? 1.f : 0.f;
        int2 e0 = g_edge[i], e1 = g_edge[i1], e2 = g_edge[i2], e3 = g_edge[i3];
        float4 f0 = *(const float4*)(feats + (size_t)e0.x * FD + coff);
        float4 f1 = *(const float4*)(feats + (size_t)e1.x * FD + coff);
        float4 f2 = *(const float4*)(feats + (size_t)e2.x * FD + coff);
        float4 f3 = *(const float4*)(feats + (size_t)e3.x * FD + coff);
        float4 r0 = *(const float4*)(g_relnorm + (size_t)e0.y * FF + lane * 4);
        float4 r1 = *(const float4*)(g_relnorm + (size_t)e1.y * FF + lane * 4);
        float4 r2 = *(const float4*)(g_relnorm + (size_t)e2.y * FF + lane * 4);
        float4 r3 = *(const float4*)(g_relnorm + (size_t)e3.y * FF + lane * 4);
        float p0 = f0.x * r0.x + f0.y * r0.y + f0.z * r0.z + f0.w * r0.w;
        float p1 = f1.x * r1.x + f1.y * r1.y + f1.z * r1.z + f1.w * r1.w;
        float p2 = f2.x * r2.x + f2.y * r2.y + f2.z * r2.z + f2.w * r2.w;
        float p3 = f3.x * r3.x + f3.y * r3.y + f3.z * r3.z + f3.w * r3.w;
#pragma unroll
        for (int o = 16; o; o >>= 1) {
            p0 += __shfl_xor_sync(0xffffffffu, p0, o);
            p1 += __shfl_xor_sync(0xffffffffu, p1, o);
            p2 += __shfl_xor_sync(0xffffffffu, p2, o);
            p3 += __shfl_xor_sync(0xffffffffu, p3, o);
        }
        float w0 = __expf(tt[e0.y] - smax) * invs;
        float w1 = __expf(tt[e1.y] - smax) * invs * a1;
        float w2 = __expf(tt[e2.y] - smax) * invs * a2;
        float w3 = __expf(tt[e3.y] - smax) * invs * a3;
        float c0 = 2.f * p0 * w0, c1 = 2.f * p1 * w1;
        float c2 = 2.f * p2 * w2, c3 = 2.f * p3 * w3;
        acc.x += w0 * f0.x - c0 * r0.x + w1 * f1.x - c1 * r1.x
               + w2 * f2.x - c2 * r2.x + w3 * f3.x - c3 * r3.x;
        acc.y += w0 * f0.y - c0 * r0.y + w1 * f1.y - c1 * r1.y
               + w2 * f2.y - c2 * r2.y + w3 * f3.y - c3 * r3.y;
        acc.z += w0 * f0.z - c0 * r0.z + w1 * f1.z - c1 * r1.z
               + w2 * f2.z - c2 * r2.z + w3 * f3.z - c3 * r3.z;
        acc.w += w0 * f0.w - c0 * r0.w + w1 * f1.w - c1 * r1.w
               + w2 * f2.w - c2 * r2.w + w3 * f3.w - c3 * r3.w;
    }
    float* o = &g_out[dual][(size_t)w * FD + (layer + 1) * FF + lane * 4];
    o[0] = tanhf(acc.x); o[1] = tanhf(acc.y);
    o[2] = tanhf(acc.z); o[3] = tanhf(acc.w);
}

// ------------------------ proxy normalization -----------------------------------
__global__ void pnorm_kernel(const float* __restrict__ pe, const float* __restrict__ pr) {
    int w = (blockIdx.x * blockDim.x + threadIdx.x) >> 5;
    if (w >= 2 * PP) return;
    int lane = threadIdx.x & 31;
    int dual = (w >= PP) ? 1 : 0;
    int row = w & (PP - 1);
    const float* p = dual ? pr : pe;
    float v[12];
    float ss = 0;
#pragma unroll
    for (int j = 0; j < 12; j++) {
        v[j] = p[(size_t)row * FD + lane + 32 * j];
        ss += v[j] * v[j];
    }
    ss = wsum(ss);
    float inv = 1.f / fmaxf(sqrtf(ss), EPSV);
#pragma unroll
    for (int j = 0; j < 12; j++)
        g_pn[dual][(size_t)row * FD + lane + 32 * j] = v[j] * inv;
}

// ------------------------ W -> bf16 hi/lo split ---------------------------------
__global__ void wconv_kernel(const float* __restrict__ We, const float* __restrict__ Wr) {
    int i = blockIdx.x * blockDim.x + threadIdx.x;
    if (i >= 2 * FD * FD) return;
    int dual = i >= FD * FD;
    int j = i - dual * FD * FD;
    float v = (dual ? Wr : We)[j];
    __nv_bfloat16 h = __float2bfloat16(v);
    __nv_bfloat16 l = __float2bfloat16(v - __bfloat162float(h));
    g_wh[dual][j] = h;
    g_wl[dual][j] = l;
}

// ---------- S = l2norm(O) @ Pn^T, fused row-softmax -> g_att --------------------
__global__ void __launch_bounds__(256) s_kernel(int N_) {
    __shared__ float As[32][128];
    __shared__ float Bs[32][68];
    int dual = blockIdx.z;
    const float* A = g_out[dual];
    const float* B = g_pn[dual];
    int tid = threadIdx.x;
    int tx = tid & 15, ty = tid >> 4;
    int rowBase = blockIdx.x * 128;
    unsigned long long acc2[8][2];
    float ss[8];
#pragma unroll
    for (int i = 0; i < 8; i++) { acc2[i][0] = 0ull; acc2[i][1] = 0ull; ss[i] = 0.f; }

    for (int k0 = 0; k0 < FD; k0 += 32) {
#pragma unroll
        for (int ld = 0; ld < 4; ld++) {
            int slot = tid + 256 * ld;
            int r = slot >> 3, c4 = slot & 7;
            int grow = rowBase + r;
            float4 v = (grow < N_) ? *(const float4*)(A + (size_t)grow * FD + k0 + c4 * 4)
                                   : make_float4(0, 0, 0, 0);
            As[c4 * 4 + 0][r] = v.x;
            As[c4 * 4 + 1][r] = v.y;
            As[c4 * 4 + 2][r] = v.z;
            As[c4 * 4 + 3][r] = v.w;
        }
#pragma unroll
        for (int ld = 0; ld < 2; ld++) {
            int slot = tid + 256 * ld;
            int p = slot >> 3, c4 = slot & 7;
            float4 v = *(const float4*)(B + (size_t)p * FD + k0 + c4 * 4);
            Bs[c4 * 4 + 0][p] = v.x;
            Bs[c4 * 4 + 1][p] = v.y;
            Bs[c4 * 4 + 2][p] = v.z;
            Bs[c4 * 4 + 3][p] = v.w;
        }
        __syncthreads();
#pragma unroll
        for (int k = 0; k < 32; k++) {
            float ra[8];
            *(float4*)(&ra[0]) = *(const float4*)(&As[k][ty * 8]);
            *(float4*)(&ra[4]) = *(const float4*)(&As[k][ty * 8 + 4]);
            ulonglong2 b = *(const ulonglong2*)(&Bs[k][tx * 4]);
#pragma unroll
            for (int i = 0; i < 8; i++) {
                unsigned long long a2 = pack2(ra[i]);
                fma2(acc2[i][0], a2, b.x);
                fma2(acc2[i][1], a2, b.y);
                ss[i] = fmaf(ra[i], ra[i], ss[i]);
            }
        }
        __syncthreads();
    }
    float* ATT = g_att[dual];
#pragma unroll
    for (int i = 0; i < 8; i++) {
        float inv = 1.f / fmaxf(sqrtf(ss[i]), EPSV);
        float v0 = lo32(acc2[i][0]) * inv;
        float v1 = hi32(acc2[i][0]) * inv;
        float v2 = lo32(acc2[i][1]) * inv;
        float v3 = hi32(acc2[i][1]) * inv;
        float m = fmaxf(fmaxf(v0, v1), fmaxf(v2, v3));
#pragma unroll
        for (int o = 8; o; o >>= 1) m = fmaxf(m, __shfl_xor_sync(0xffffffffu, m, o));
        float e0 = __expf(v0 - m), e1 = __expf(v1 - m);
        float e2 = __expf(v2 - m), e3 = __expf(v3 - m);
        float sm = e0 + e1 + e2 + e3;
#pragma unroll
        for (int o = 8; o; o >>= 1) sm += __shfl_xor_sync(0xffffffffu, sm, o);
        float r = 1.f / sm;
        int n = rowBase + ty * 8 + i;
        if (n < N_) {
            float* d = ATT + (size_t)n * PP + tx * 4;
            d[0] = e0 * r; d[1] = e1 * r; d[2] = e2 * r; d[3] = e3 * r;
        }
    }
}

// ------- PF = O - Att @ P  [N,384] GEMM (K=64) -> bf16 hi/lo --------------------
__global__ void __launch_bounds__(256) pf_kernel(const float* __restrict__ pe,
                                                 const float* __restrict__ pr, int N_) {
    __shared__ float As[32][128];
    __shared__ float Bs[32][128];
    int dual = blockIdx.z;
    const float* P = dual ? pr : pe;
    const float* A = g_att[dual];
    int tid = threadIdx.x;
    int tx = tid & 15, ty = tid >> 4;
    int rowBase = blockIdx.y * 128;
    int colBase = blockIdx.x * 128;
    unsigned long long acc2[8][4];
#pragma unroll
    for (int i = 0; i < 8; i++)
#pragma unroll
        for (int j = 0; j < 4; j++) acc2[i][j] = 0ull;

    for (int k0 = 0; k0 < PP; k0 += 32) {
#pragma unroll
        for (int ld = 0; ld < 4; ld++) {
            int slot = tid + 256 * ld;
            int r = slot >> 3, c4 = slot & 7;
            int grow = rowBase + r;
            float4 v = (grow < N_) ? *(const float4*)(A + (size_t)grow * PP + k0 + c4 * 4)
                                   : make_float4(0, 0, 0, 0);
            As[c4 * 4 + 0][r] = v.x;
            As[c4 * 4 + 1][r] = v.y;
            As[c4 * 4 + 2][r] = v.z;
            As[c4 * 4 + 3][r] = v.w;
        }
#pragma unroll
        for (int ld = 0; ld < 4; ld++) {
            int slot = tid + 256 * ld;
            int r = slot >> 5, c4 = slot & 31;
            float4 v = *(const float4*)(P + (size_t)(k0 + r) * FD + colBase + c4 * 4);
            *(float4*)(&Bs[r][c4 * 4]) = v;
        }
        __syncthreads();
#pragma unroll
        for (int k = 0; k < 32; k++) {
            float ra[8];
            *(float4*)(&ra[0]) = *(const float4*)(&As[k][ty * 8]);
            *(float4*)(&ra[4]) = *(const float4*)(&As[k][ty * 8 + 4]);
            ulonglong2 b0 = *(const ulonglong2*)(&Bs[k][tx * 8]);
            ulonglong2 b1 = *(const ulonglong2*)(&Bs[k][tx * 8 + 4]);
#pragma unroll
            for (int i = 0; i < 8; i++) {
                unsigned long long a2 = pack2(ra[i]);
                fma2(acc2[i][0], a2, b0.x);
                fma2(acc2[i][1], a2, b0.y);
                fma2(acc2[i][2], a2, b1.x);
                fma2(acc2[i][3], a2, b1.y);
            }
        }
        __syncthreads();
    }
    const float* O = g_out[dual];
#pragma unroll
    for (int i = 0; i < 8; i++) {
        int n = rowBase + ty * 8 + i;
        if (n >= N_) continue;
        int c = colBase + tx * 8;
        const float* orow = O + (size_t)n * FD + c;
        float accv[8];
        accv[0] = lo32(acc2[i][0]); accv[1] = hi32(acc2[i][0]);
        accv[2] = lo32(acc2[i][1]); accv[3] = hi32(acc2[i][1]);
        accv[4] = lo32(acc2[i][2]); accv[5] = hi32(acc2[i][2]);
        accv[6] = lo32(acc2[i][3]); accv[7] = hi32(acc2[i][3]);
        __nv_bfloat162 hh[4], ll[4];
#pragma unroll
        for (int q = 0; q < 4; q++) {
            float va = orow[2 * q] - accv[2 * q];
            float vb = orow[2 * q + 1] - accv[2 * q + 1];
            __nv_bfloat16 ha = __float2bfloat16(va);
            __nv_bfloat16 hb = __float2bfloat16(vb);
            __nv_bfloat16 la = __float2bfloat16(va - __bfloat162float(ha));
            __nv_bfloat16 lb = __float2bfloat16(vb - __bfloat162float(hb));
            hh[q] = __nv_bfloat162(ha, hb);
            ll[q] = __nv_bfloat162(la, lb);
        }
        __nv_bfloat162* DH = (__nv_bfloat162*)(g_pfh[dual] + (size_t)n * FD + c);
        __nv_bfloat162* DL = (__nv_bfloat162*)(g_pfl[dual] + (size_t)n * FD + c);
#pragma unroll
        for (int q = 0; q < 4; q++) { DH[q] = hh[q]; DL[q] = ll[q]; }
    }
}

// ------- F2: WMMA bf16 3-term split GEMM + sigmoid blend ------------------------
// C[128,64] tile = PF[128,384] @ W[384, 64cols]; terms AhBh + AlBh + AhBl.
#define ALD 40
#define SLD 68
__global__ void __launch_bounds__(256) f2_wmma_kernel(const float* __restrict__ be,
                                                      const float* __restrict__ br,
                                                      float* __restrict__ out, int N_) {
    __shared__ __align__(16) char smraw[34816];   // max(tiles 30720, stage 34816)
    __nv_bfloat16* Ah = (__nv_bfloat16*)smraw;           // [128][ALD]
    __nv_bfloat16* Al = Ah + 128 * ALD;
    __nv_bfloat16* Bh = Al + 128 * ALD;                  // [64][ALD] (n-major, k inner)
    __nv_bfloat16* Bl = Bh + 64 * ALD;
    float* stage = (float*)smraw;                        // [128][SLD]

    int tid = threadIdx.x, wid = tid >> 5, lane = tid & 31;
    int warpM = wid & 3, warpN = wid >> 2;               // 4 x 2 warps
    int colBase = blockIdx.x * 64;
    int rowBase = blockIdx.y * 128;
    int dual = blockIdx.z;
    const float* bias = dual ? br : be;
    const __nv_bfloat16* PH = g_pfh[dual];
    const __nv_bfloat16* PL = g_pfl[dual];
    const __nv_bfloat16* WH = g_wh[dual];
    const __nv_bfloat16* WL = g_wl[dual];

    wmma::fragment<wmma::accumulator, 16, 16, 16, float> c[2][2];
#pragma unroll
    for (int i = 0; i < 2; i++)
#pragma unroll
        for (int j = 0; j < 2; j++) wmma::fill_fragment(c[i][j], 0.f);

    for (int k0 = 0; k0 < FD; k0 += 32) {
        // A tiles: 128 rows x 32 k bf16 (hi & lo) as uint pairs
        for (int s = tid; s < 2048; s += 256) {
            int r = s >> 4, cu = s & 15;
            int gr = rowBase + r;
            unsigned vh = 0, vl = 0;
            if (gr < N_) {
                size_t gi = ((size_t)gr * FD + k0) / 2 + cu;
                vh = ((const unsigned*)PH)[gi];
                vl = ((const unsigned*)PL)[gi];
            }
            ((unsigned*)(Ah + r * ALD))[cu] = vh;
            ((unsigned*)(Al + r * ALD))[cu] = vl;
        }
        // B tiles (transposed): Bh[n][k] = W[k0+k][colBase+n]
        for (int s = tid; s < 64 * 32; s += 256) {
            int n = s & 63, k = s >> 6;
            size_t gi = (size_t)(k0 + k) * FD + colBase + n;
            Bh[n * ALD + k] = WH[gi];
            Bl[n * ALD + k] = WL[gi];
        }
        __syncthreads();
#pragma unroll
        for (int ks = 0; ks < 32; ks += 16) {
            wmma::fragment<wmma::matrix_a, 16, 16, 16, __nv_bfloat16, wmma::row_major> a[2];
            wmma::fragment<wmma::matrix_b, 16, 16, 16, __nv_bfloat16, wmma::col_major> b[2];
            // term 1: Ah x Bh
#pragma unroll
            for (int i = 0; i < 2; i++)
                wmma::load_matrix_sync(a[i], Ah + (warpM * 32 + i * 16) * ALD + ks, ALD);
#pragma unroll
            for (int j = 0; j < 2; j++)
                wmma::load_matrix_sync(b[j], Bh + (warpN * 32 + j * 16) * ALD + ks, ALD);
#pragma unroll
            for (int i = 0; i < 2; i++)
#pragma unroll
                for (int j = 0; j < 2; j++) wmma::mma_sync(c[i][j], a[i], b[j], c[i][j]);
            // term 2: Al x Bh
#pragma unroll
            for (int i = 0; i < 2; i++)
                wmma::load_matrix_sync(a[i], Al + (warpM * 32 + i * 16) * ALD + ks, ALD);
#pragma unroll
            for (int i = 0; i < 2; i++)
#pragma unroll
                for (int j = 0; j < 2; j++) wmma::mma_sync(c[i][j], a[i], b[j], c[i][j]);
            // term 3: Ah x Bl
#pragma unroll
            for (int i = 0; i < 2; i++)
                wmma::load_matrix_sync(a[i], Ah + (warpM * 32 + i * 16) * ALD + ks, ALD);
#pragma unroll
            for (int j = 0; j < 2; j++)
                wmma::load_matrix_sync(b[j], Bl + (warpN * 32 + j * 16) * ALD + ks, ALD);
#pragma unroll
            for (int i = 0; i < 2; i++)
#pragma unroll
                for (int j = 0; j < 2; j++) wmma::mma_sync(c[i][j], a[i], b[j], c[i][j]);
        }
        __syncthreads();
    }

    // stage C to smem (reuse tile memory)
#pragma unroll
    for (int i = 0; i < 2; i++)
#pragma unroll
        for (int j = 0; j < 2; j++)
            wmma::store_matrix_sync(stage + (warpM * 32 + i * 16) * SLD + warpN * 32 + j * 16,
                                    c[i][j], SLD, wmma::mem_row_major);
    __syncthreads();

    // epilogue: sigmoid gate + blend, fully coalesced (lane -> 2 cols)
    const float* O = g_out[dual];
    const __nv_bfloat162* PH2 = (const __nv_bfloat162*)PH;
    const __nv_bfloat162* PL2 = (const __nv_bfloat162*)PL;
#pragma unroll
    for (int i = 0; i < 16; i++) {
        int r = wid * 16 + i;
        int n = rowBase + r;
        if (n >= N_) continue;
        int c0 = colBase + lane * 2;
        float2 acc = *(float2*)(stage + r * SLD + lane * 2);
        float2 bv = *(const float2*)(bias + c0);
        float2 ov = *(const float2*)(O + (size_t)n * FD + c0);
        size_t pi = ((size_t)n * FD + c0) >> 1;
        __nv_bfloat162 h0 = PH2[pi];
        __nv_bfloat162 l0 = PL2[pi];
        float pf0 = __bfloat162float(h0.x) + __bfloat162float(l0.x);
        float pf1 = __bfloat162float(h0.y) + __bfloat162float(l0.y);
        float g0 = 1.f / (1.f + __expf(-(acc.x + bv.x)));
        float g1 = 1.f / (1.f + __expf(-(acc.y + bv.y)));
        float2 res;
        res.x = g0 * ov.x + (1.f - g0) * pf0;
        res.y = g1 * ov.y + (1.f - g1) * pf1;
        *(float2*)(out + (size_t)n * (2 * FD) + dual * FD + c0) = res;
    }
}

// ------------------------ launch ------------------------------------------------
extern "C" void kernel_launch(void* const* d_in, const int* in_sizes, int n_in,
                              void* d_out, int out_size) {
    const float* ent_emb = (const float*)d_in[0];
    const float* rel_emb = (const float*)d_in[1];
    const int* edge_src  = (const int*)d_in[2];
    const int* edge_dst  = (const int*)d_in[3];
    const int* edge_rel  = (const int*)d_in[4];
    const float* attn_e  = (const float*)d_in[5];
    const float* gate_e  = (const float*)d_in[6];
    const float* proxy_e = (const float*)d_in[7];
    const float* bias_e  = (const float*)d_in[8];
    const float* attn_r  = (const float*)d_in[9];
    const float* gate_r  = (const float*)d_in[10];
    const float* proxy_r = (const float*)d_in[11];
    const float* bias_r  = (const float*)d_in[12];

    int N_ = in_sizes[0] / FF;
    int R_ = in_sizes[1] / FF;
    int E_ = in_sizes[2];
    float* out = (float*)d_out;

    zero_deg_kernel<<<(N_ + 255) / 256, 256>>>(N_);
    count_kernel<<<(E_ + 255) / 256, 256>>>(edge_dst, E_);
    scan_kernel<<<1, 1024>>>(N_);
    scatter_kernel<<<(E_ + 255) / 256, 256>>>(edge_dst, edge_src, edge_rel, E_);
    relnorm_kernel<<<(R_ * 32 + 255) / 256, 256>>>(rel_emb, attn_e, attn_r, R_);
    stats_kernel<<<1184, 256>>>(N_, R_);
    init_kernel<<<(N_ * 32 + 255) / 256, 256>>>(ent_emb, rel_emb, N_);
    wconv_kernel<<<(2 * FD * FD + 255) / 256, 256>>>(gate_e, gate_r);

    int lgrid = (2 * N_ * 32 + 255) / 256;
    layer_kernel<<<lgrid, 256>>>(0, N_, R_);
    layer_kernel<<<lgrid, 256>>>(1, N_, R_);

    pnorm_kernel<<<16, 256>>>(proxy_e, proxy_r);

    dim3 gs((N_ + 127) / 128, 1, 2);
    s_kernel<<<gs, 256>>>(N_);

    dim3 gpf(FD / 128, (N_ + 127) / 128, 2);
    pf_kernel<<<gpf, 256>>>(proxy_e, proxy_r, N_);

    dim3 g2(FD / 64, (N_ + 127) / 128, 2);
    f2_wmma_kernel<<<g2, 256>>>(bias_e, bias_r, out, N_);
}